// round 5
// baseline (speedup 1.0000x reference)
#include <cuda_runtime.h>
#include <cuda_fp16.h>
#include <mma.h>
#include <math.h>

using namespace nvcuda;

#define NN 50000
#define NNP 50048          // padded rows for 128-row GEMM tiles
#define EE 1600000
#define VV 100000
#define DD 128
#define OO 64
#define TOT (NN*16)
#define NB 49   // ceil(NN/1024)

// ---------------- scratch (static device globals; no allocs allowed) ----------
__device__ int    g_cnt[NN];
__device__ int    g_offs[NN + 1];
__device__ int    g_csr[EE];
__device__ int    g_bsum[64];
__device__ int    g_bpre[64];
__device__ float  g_isqrt[NN];
__device__ float  g_dinv[NN];
__device__ __half g_xh[NN * DD];    // embedding output (fp16)
__device__ __half g_ph[NNP * DD];   // aggregation output (fp16, GEMM A operand)
__device__ __half g_hh[NNP * DD];   // relu(gemm1) (fp16)
__device__ __half g_zh[NN * OO];    // z (fp16)
__device__ __half g_w1h[DD * DD];   // W1 fp16
__device__ __half g_wabh[DD * DD];  // [Wmu|Wls] fp16

// ---------------- CSR build ---------------------------------------------------
__global__ void k_hist(const int* __restrict__ dst) {
    int base = (blockIdx.x * blockDim.x + threadIdx.x) * 4;
    if (base + 4 <= EE) {
        int4 d = *(const int4*)(dst + base);
        atomicAdd(&g_cnt[d.x], 1);
        atomicAdd(&g_cnt[d.y], 1);
        atomicAdd(&g_cnt[d.z], 1);
        atomicAdd(&g_cnt[d.w], 1);
    } else {
        for (int e = base; e < EE; e++) atomicAdd(&g_cnt[dst[e]], 1);
    }
}

__global__ __launch_bounds__(1024) void k_scan1() {
    __shared__ int s[1024];
    int t = threadIdx.x;
    int i = blockIdx.x * 1024 + t;
    int v = (i < NN) ? g_cnt[i] : 0;
    s[t] = v;
    __syncthreads();
    #pragma unroll
    for (int off = 1; off < 1024; off <<= 1) {
        int u = (t >= off) ? s[t - off] : 0;
        __syncthreads();
        s[t] += u;
        __syncthreads();
    }
    if (i < NN) g_offs[i] = s[t] - v;
    if (t == 1023) g_bsum[blockIdx.x] = s[1023];
}

__global__ void k_scan2() {
    __shared__ int s[64];
    int t = threadIdx.x;
    int v = (t < NB) ? g_bsum[t] : 0;
    s[t] = v;
    __syncthreads();
    #pragma unroll
    for (int off = 1; off < 64; off <<= 1) {
        int u = (t >= off) ? s[t - off] : 0;
        __syncthreads();
        s[t] += u;
        __syncthreads();
    }
    g_bpre[t] = s[t] - v;
}

__global__ void k_scan3() {
    int i = blockIdx.x * blockDim.x + threadIdx.x;
    if (i >= NN) return;
    g_offs[i] += g_bpre[i >> 10];
    int c = g_cnt[i];
    float deg = (float)(c + 1);
    g_isqrt[i] = rsqrtf(deg);
    g_dinv[i]  = 1.0f / deg;
    g_cnt[i]   = 0;
    if (i == 0) g_offs[NN] = EE;
}

__global__ void k_scatter(const int* __restrict__ src, const int* __restrict__ dst) {
    int base = (blockIdx.x * blockDim.x + threadIdx.x) * 4;
    if (base + 4 <= EE) {
        int4 d = *(const int4*)(dst + base);
        int4 s = *(const int4*)(src + base);
        int p0 = g_offs[d.x] + atomicAdd(&g_cnt[d.x], 1); g_csr[p0] = s.x;
        int p1 = g_offs[d.y] + atomicAdd(&g_cnt[d.y], 1); g_csr[p1] = s.y;
        int p2 = g_offs[d.z] + atomicAdd(&g_cnt[d.z], 1); g_csr[p2] = s.z;
        int p3 = g_offs[d.w] + atomicAdd(&g_cnt[d.w], 1); g_csr[p3] = s.w;
    } else {
        for (int e = base; e < EE; e++) {
            int d = dst[e];
            int pos = g_offs[d] + atomicAdd(&g_cnt[d], 1);
            g_csr[pos] = src[e];
        }
    }
}

// ---------------- weight fp16 conversion --------------------------------------
__global__ void k_cvtw1(const float* __restrict__ W) {
    int i = blockIdx.x * 256 + threadIdx.x;
    if (i < DD * DD) g_w1h[i] = __float2half(W[i]);
}
__global__ void k_cvtwab(const float* __restrict__ Wa, const float* __restrict__ Wb) {
    int i = blockIdx.x * 256 + threadIdx.x;
    if (i < DD * DD) {
        int r = i >> 7, c = i & 127;
        g_wabh[i] = __float2half(c < 64 ? Wa[r * 64 + c] : Wb[r * 64 + (c - 64)]);
    }
}

// ---------------- EmbeddingBag(sum, weighted) + L2 normalize -> fp16 ----------
__global__ void k_embed(const int* __restrict__ fidx, const int* __restrict__ foff,
                        const float* __restrict__ fw, const float* __restrict__ emb) {
    int w = (blockIdx.x * blockDim.x + threadIdx.x) >> 5;
    int lane = threadIdx.x & 31;
    if (w >= NN) return;
    int start = foff[w];
    int end = (w + 1 < NN) ? foff[w + 1] : TOT;
    float4 acc = make_float4(0.f, 0.f, 0.f, 0.f);
    int k = start;
    for (; k + 4 <= end; k += 4) {
        int i0 = fidx[k], i1 = fidx[k+1], i2 = fidx[k+2], i3 = fidx[k+3];
        float w0 = fw[k], w1 = fw[k+1], w2 = fw[k+2], w3 = fw[k+3];
        float4 v0 = ((const float4*)emb)[i0 * 32 + lane];
        float4 v1 = ((const float4*)emb)[i1 * 32 + lane];
        float4 v2 = ((const float4*)emb)[i2 * 32 + lane];
        float4 v3 = ((const float4*)emb)[i3 * 32 + lane];
        acc.x = fmaf(w0, v0.x, fmaf(w1, v1.x, fmaf(w2, v2.x, fmaf(w3, v3.x, acc.x))));
        acc.y = fmaf(w0, v0.y, fmaf(w1, v1.y, fmaf(w2, v2.y, fmaf(w3, v3.y, acc.y))));
        acc.z = fmaf(w0, v0.z, fmaf(w1, v1.z, fmaf(w2, v2.z, fmaf(w3, v3.z, acc.z))));
        acc.w = fmaf(w0, v0.w, fmaf(w1, v1.w, fmaf(w2, v2.w, fmaf(w3, v3.w, acc.w))));
    }
    for (; k < end; k++) {
        int idx = fidx[k];
        float wt = fw[k];
        float4 v = ((const float4*)emb)[idx * 32 + lane];
        acc.x = fmaf(wt, v.x, acc.x);
        acc.y = fmaf(wt, v.y, acc.y);
        acc.z = fmaf(wt, v.z, acc.z);
        acc.w = fmaf(wt, v.w, acc.w);
    }
    float ss = acc.x * acc.x + acc.y * acc.y + acc.z * acc.z + acc.w * acc.w;
    for (int o = 16; o > 0; o >>= 1) ss += __shfl_xor_sync(0xffffffffu, ss, o);
    float inv = 1.0f / fmaxf(sqrtf(ss), 1e-12f);
    __half2 h0 = __floats2half2_rn(acc.x * inv, acc.y * inv);
    __half2 h1 = __floats2half2_rn(acc.z * inv, acc.w * inv);
    uint2 u;
    u.x = *(unsigned*)&h0;
    u.y = *(unsigned*)&h1;
    ((uint2*)g_xh)[w * 32 + lane] = u;
}

// ---------------- GCN aggregation: fp16 gather, fp32 accumulate, fp16 out -----
__global__ void k_agg(const __half* __restrict__ in, __half* __restrict__ out) {
    int w = (blockIdx.x * blockDim.x + threadIdx.x) >> 5;
    int lane = threadIdx.x & 31;
    if (w >= NN) return;
    int lo = g_offs[w], hi = g_offs[w + 1];
    const uint2* in2 = (const uint2*)in;
    float4 acc = make_float4(0.f, 0.f, 0.f, 0.f);
    int p = lo;
    for (; p + 8 <= hi; p += 8) {
        int j[8];
        float wj[8];
        uint2 u[8];
        #pragma unroll
        for (int q = 0; q < 8; q++) j[q] = g_csr[p + q];
        #pragma unroll
        for (int q = 0; q < 8; q++) wj[q] = g_isqrt[j[q]];
        #pragma unroll
        for (int q = 0; q < 8; q++) u[q] = in2[j[q] * 32 + lane];
        #pragma unroll
        for (int q = 0; q < 8; q++) {
            float2 f0 = __half22float2(*(__half2*)&u[q].x);
            float2 f1 = __half22float2(*(__half2*)&u[q].y);
            acc.x = fmaf(wj[q], f0.x, acc.x);
            acc.y = fmaf(wj[q], f0.y, acc.y);
            acc.z = fmaf(wj[q], f1.x, acc.z);
            acc.w = fmaf(wj[q], f1.y, acc.w);
        }
    }
    for (; p < hi; p++) {
        int jj = g_csr[p];
        float wj = g_isqrt[jj];
        uint2 u = in2[jj * 32 + lane];
        float2 f0 = __half22float2(*(__half2*)&u.x);
        float2 f1 = __half22float2(*(__half2*)&u.y);
        acc.x = fmaf(wj, f0.x, acc.x);
        acc.y = fmaf(wj, f0.y, acc.y);
        acc.z = fmaf(wj, f1.x, acc.z);
        acc.w = fmaf(wj, f1.y, acc.w);
    }
    float si = g_isqrt[w], di = g_dinv[w];
    uint2 us = in2[w * 32 + lane];
    float2 s0 = __half22float2(*(__half2*)&us.x);
    float2 s1 = __half22float2(*(__half2*)&us.y);
    __half2 h0 = __floats2half2_rn(acc.x * si + s0.x * di, acc.y * si + s0.y * di);
    __half2 h1 = __floats2half2_rn(acc.z * si + s1.x * di, acc.w * si + s1.y * di);
    uint2 u;
    u.x = *(unsigned*)&h0;
    u.y = *(unsigned*)&h1;
    ((uint2*)out)[w * 32 + lane] = u;
}

// ---------------- GEMM1 (tensor cores): h = relu(A @ W1h + b1) -> fp16 --------
// 256 thr = 8 warps (4x2), CTA tile 128x128, warp tile 32x64, wmma 16x16x16
__global__ __launch_bounds__(256) void k_gemm1_t(const __half* __restrict__ A,
                                                 const float* __restrict__ bias,
                                                 __half* __restrict__ hout) {
    __shared__ float sC[8][16][68];          // per-warp 16x64 (+4 pad) = 34816 B
    int w = threadIdx.x >> 5, lane = threadIdx.x & 31;
    int wr = w >> 1, wc = w & 1;
    int row0 = blockIdx.x * 128 + wr * 32;
    int col0 = wc * 64;
    const __half* B = g_w1h;

    wmma::fragment<wmma::accumulator, 16, 16, 16, float> c[2][4];
    #pragma unroll
    for (int i = 0; i < 2; i++)
        #pragma unroll
        for (int j = 0; j < 4; j++) wmma::fill_fragment(c[i][j], 0.f);

    #pragma unroll
    for (int k0 = 0; k0 < 8; k0++) {
        wmma::fragment<wmma::matrix_a, 16, 16, 16, half, wmma::row_major> a[2];
        wmma::fragment<wmma::matrix_b, 16, 16, 16, half, wmma::row_major> b[4];
        #pragma unroll
        for (int i = 0; i < 2; i++)
            wmma::load_matrix_sync(a[i], A + (size_t)(row0 + i * 16) * 128 + k0 * 16, 128);
        #pragma unroll
        for (int j = 0; j < 4; j++)
            wmma::load_matrix_sync(b[j], B + (size_t)(k0 * 16) * 128 + col0 + j * 16, 128);
        #pragma unroll
        for (int i = 0; i < 2; i++)
            #pragma unroll
            for (int j = 0; j < 4; j++)
                wmma::mma_sync(c[i][j], a[i], b[j], c[i][j]);
    }

    #pragma unroll
    for (int i = 0; i < 2; i++) {
        #pragma unroll
        for (int j = 0; j < 4; j++)
            wmma::store_matrix_sync(&sC[w][0][j * 16], c[i][j], 68, wmma::mem_row_major);
        __syncwarp();
        int r = lane >> 1, ch = (lane & 1) * 32;
        int gr = row0 + i * 16 + r;
        if (gr < NN) {
            __align__(16) __half tmp[32];
            #pragma unroll
            for (int cc = 0; cc < 32; cc++) {
                float v = sC[w][r][ch + cc] + bias[col0 + ch + cc];
                tmp[cc] = __float2half(fmaxf(v, 0.f));
            }
            uint4* dstp = (uint4*)(hout + (size_t)gr * 128 + col0 + ch);
            const uint4* srcp = (const uint4*)tmp;
            #pragma unroll
            for (int q = 0; q < 4; q++) dstp[q] = srcp[q];
        }
        __syncwarp();
    }
}

// ---------------- GEMM2 (tensor cores) + fused z -> fp16 -----------------------
// C = A @ [Wmu|Wls]; z = (C[:, :64]+bmu) + noise * exp(C[:, 64:]+bls)
__global__ __launch_bounds__(256) void k_gemm2z_t(const __half* __restrict__ A,
                                                  const float* __restrict__ bmu,
                                                  const float* __restrict__ bls,
                                                  const float* __restrict__ noise) {
    __shared__ float sC[4][16][132];         // per warp-pair 16x128 (+4 pad) = 33792 B
    int w = threadIdx.x >> 5, lane = threadIdx.x & 31;
    int wr = w >> 1, wc = w & 1;
    int row0 = blockIdx.x * 128 + wr * 32;
    int col0 = wc * 64;
    const __half* B = g_wabh;

    wmma::fragment<wmma::accumulator, 16, 16, 16, float> c[2][4];
    #pragma unroll
    for (int i = 0; i < 2; i++)
        #pragma unroll
        for (int j = 0; j < 4; j++) wmma::fill_fragment(c[i][j], 0.f);

    #pragma unroll
    for (int k0 = 0; k0 < 8; k0++) {
        wmma::fragment<wmma::matrix_a, 16, 16, 16, half, wmma::row_major> a[2];
        wmma::fragment<wmma::matrix_b, 16, 16, 16, half, wmma::row_major> b[4];
        #pragma unroll
        for (int i = 0; i < 2; i++)
            wmma::load_matrix_sync(a[i], A + (size_t)(row0 + i * 16) * 128 + k0 * 16, 128);
        #pragma unroll
        for (int j = 0; j < 4; j++)
            wmma::load_matrix_sync(b[j], B + (size_t)(k0 * 16) * 128 + col0 + j * 16, 128);
        #pragma unroll
        for (int i = 0; i < 2; i++)
            #pragma unroll
            for (int j = 0; j < 4; j++)
                wmma::mma_sync(c[i][j], a[i], b[j], c[i][j]);
    }

    #pragma unroll
    for (int i = 0; i < 2; i++) {
        #pragma unroll
        for (int j = 0; j < 4; j++)
            wmma::store_matrix_sync(&sC[wr][0][col0 + j * 16], c[i][j], 132, wmma::mem_row_major);
        __syncthreads();
        int tp = wc * 32 + lane;             // 0..63 within the warp-pair
        #pragma unroll 4
        for (int r = 0; r < 16; r++) {
            int gr = row0 + i * 16 + r;
            if (gr < NN) {
                float mu = sC[wr][r][tp] + bmu[tp];
                float ls = sC[wr][r][64 + tp] + bls[tp];
                float zz = fmaf(noise[(size_t)gr * 64 + tp], expf(ls), mu);
                g_zh[(size_t)gr * 64 + tp] = __float2half(zz);
            }
        }
        __syncthreads();
    }
}

// ---------------- decoder: logits[e] = dot(z[src], z[dst]), fp16 z ------------
__global__ void k_dec(const int* __restrict__ src, const int* __restrict__ dst,
                      float* __restrict__ out) {
    int g = blockIdx.x * (blockDim.x >> 3) + (threadIdx.x >> 3);
    int l = threadIdx.x & 7;
    if (g >= EE) return;
    int s = src[g], d = dst[g];
    uint4 ua = ((const uint4*)g_zh)[s * 8 + l];
    uint4 ub = ((const uint4*)g_zh)[d * 8 + l];
    float v = 0.f;
    const unsigned* pa = &ua.x;
    const unsigned* pb = &ub.x;
    #pragma unroll
    for (int q = 0; q < 4; q++) {
        float2 fa = __half22float2(*(const __half2*)&pa[q]);
        float2 fb = __half22float2(*(const __half2*)&pb[q]);
        v = fmaf(fa.x, fb.x, v);
        v = fmaf(fa.y, fb.y, v);
    }
    v += __shfl_xor_sync(0xffffffffu, v, 4);
    v += __shfl_xor_sync(0xffffffffu, v, 2);
    v += __shfl_xor_sync(0xffffffffu, v, 1);
    if (l == 0) out[g] = v;
}

// ---------------- launch -------------------------------------------------------
extern "C" void kernel_launch(void* const* d_in, const int* in_sizes, int n_in,
                              void* d_out, int out_size) {
    const int*   fidx  = (const int*)d_in[0];
    const int*   foff  = (const int*)d_in[1];
    const float* fw    = (const float*)d_in[2];
    const int*   edge  = (const int*)d_in[3];
    const float* noise = (const float*)d_in[4];
    const float* emb   = (const float*)d_in[5];
    const float* W1    = (const float*)d_in[6];
    const float* b1    = (const float*)d_in[7];
    const float* Wmu   = (const float*)d_in[8];
    const float* bmu   = (const float*)d_in[9];
    const float* Wls   = (const float*)d_in[10];
    const float* bls   = (const float*)d_in[11];
    float* out = (float*)d_out;

    const int* src = edge;
    const int* dst = edge + EE;

    __half *pxh = nullptr, *pph = nullptr, *phh = nullptr;
    int* pcnt = nullptr;
    cudaGetSymbolAddress((void**)&pxh, g_xh);
    cudaGetSymbolAddress((void**)&pph, g_ph);
    cudaGetSymbolAddress((void**)&phh, g_hh);
    cudaGetSymbolAddress((void**)&pcnt, g_cnt);

    static cudaStream_t s2 = nullptr;
    static cudaEvent_t evF = nullptr, evJ = nullptr;
    static bool ok = false;
    if (!s2) {
        ok = (cudaStreamCreateWithFlags(&s2, cudaStreamNonBlocking) == cudaSuccess) &&
             (cudaEventCreateWithFlags(&evF, cudaEventDisableTiming) == cudaSuccess) &&
             (cudaEventCreateWithFlags(&evJ, cudaEventDisableTiming) == cudaSuccess);
    }

    cudaStream_t se = ok ? s2 : 0;
    if (ok) {
        cudaEventRecord(evF, 0);
        cudaStreamWaitEvent(s2, evF, 0);
    }
    // branch B: weight conversion + embedding (independent of CSR build)
    k_cvtw1<<<(DD * DD + 255) / 256, 256, 0, se>>>(W1);
    k_cvtwab<<<(DD * DD + 255) / 256, 256, 0, se>>>(Wmu, Wls);
    k_embed<<<(NN + 3) / 4, 128, 0, se>>>(fidx, foff, fw, emb);
    if (ok) cudaEventRecord(evJ, s2);

    // branch A: CSR build
    cudaMemsetAsync(pcnt, 0, NN * sizeof(int), 0);
    k_hist<<<(EE / 4 + 255) / 256, 256>>>(dst);
    k_scan1<<<NB, 1024>>>();
    k_scan2<<<1, 64>>>();
    k_scan3<<<(NN + 255) / 256, 256>>>();
    k_scatter<<<(EE / 4 + 255) / 256, 256>>>(src, dst);

    if (ok) cudaStreamWaitEvent(0, evJ, 0);

    k_agg<<<(NN + 3) / 4, 128>>>(pxh, pph);                        // p1 = A~ x (fp16)
    k_gemm1_t<<<(NN + 127) / 128, 256>>>(pph, b1, phh);            // h (fp16, HMMA)
    k_agg<<<(NN + 3) / 4, 128>>>(phh, pph);                        // p2 = A~ h (fp16)
    k_gemm2z_t<<<(NN + 127) / 128, 256>>>(pph, bmu, bls, noise);   // z fused (HMMA)
    k_dec<<<(EE + 31) / 32, 256>>>(src, dst, out);
}